// round 2
// baseline (speedup 1.0000x reference)
#include <cuda_runtime.h>
#include <cuda_bf16.h>

#define Mdim 2048
#define Ndim 4096
#define COLS 28
#define NB   147
#define NT   256
#define NWARP 8
#define OUTER_IT 100
#define INNER_IT 20
#define TOTAL_IT (OUTER_IT * (INNER_IT + 1))
#define RHO_C  1.0f
#define STEP_C 5e-5f
#define RPB 14                 // rows owned per block: 147*14 = 2058 >= 2048

// Cross-block communication (device globals; no allocation allowed)
__device__ __align__(16) float    g_partial[NB][Mdim]; // per-block Ax partials
__device__ __align__(16) float    g_e[Mdim];           // reduced e = Ax - r
__device__ unsigned g_flags1[NB];                      // barrier 1 generation flags
__device__ unsigned g_flags2[NB];                      // barrier 2 generation flags

// Flag-array grid barrier: parallel arrivals, warp-0 polling, wrap-safe compare.
__device__ __forceinline__ void gbar(volatile unsigned* flags, unsigned gen) {
    __threadfence();
    __syncthreads();
    if (threadIdx.x == 0) flags[blockIdx.x] = gen;
    if (threadIdx.x < 32) {
        for (;;) {
            bool ok = true;
#pragma unroll
            for (int m = 0; m < 5; ++m) {
                int j = threadIdx.x + 32 * m;
                if (j < NB && (int)(flags[j] - gen) < 0) ok = false;
            }
            if (__all_sync(0xffffffffu, ok)) break;
        }
    }
    __syncthreads();
}

extern "C" __global__ void __launch_bounds__(NT, 1)
admm_persistent(const float* __restrict__ A,
                const float* __restrict__ b,
                const float* __restrict__ c,
                float* __restrict__ out)
{
    extern __shared__ float sm[];
    float* As   = sm;                    // g1-half of A slice: [COLS][1024] (4 rows/group)
    float* xs   = As + COLS * 1024;      // 32: x chunk
    float* cs   = xs + 32;               // 32: c chunk
    float* red  = cs + 32;               // COLS*NWARP: phase-B reduction scratch
    float* sred = red + COLS * NWARP;    // NB*RPB: owner-reduce staging
    float* rloc = sred + NB * RPB;       // RPB: owned r rows
    float* uloc = rloc + RPB;            // RPB: owned u rows
    float* bloc = uloc + RPB;            // RPB: owned b rows

    const int tid  = threadIdx.x;
    const int w    = tid >> 5;
    const int lane = tid & 31;
    const int bid  = blockIdx.x;
    const int j0   = bid * COLS;
    const int myCols = (Ndim - j0) < COLS ? (Ndim - j0) : COLS;
    const int g0 = w * 64 + lane;        // float4 row-group held in registers
    const int g1 = g0 + 32;              // float4 row-group held in SMEM
    const int h  = w * 32 + lane;        // SMEM index for g1

    // Generation base from own flag (monotonic across graph replays; zero on 1st call)
    const unsigned base1 = *((volatile unsigned*)&g_flags1[bid]);
    const unsigned base2 = *((volatile unsigned*)&g_flags2[bid]);

    // ---- load register half of A slice: rows 4*g0..4*g0+3, cols j0..j0+27 ----
    float4 areg[COLS];
#pragma unroll
    for (int j = 0; j < COLS; ++j) {
        float4 v = make_float4(0.f, 0.f, 0.f, 0.f);
        int col = j0 + j;
        if (col < Ndim) {
            v.x = A[(4 * g0 + 0) * Ndim + col];
            v.y = A[(4 * g0 + 1) * Ndim + col];
            v.z = A[(4 * g0 + 2) * Ndim + col];
            v.w = A[(4 * g0 + 3) * Ndim + col];
        }
        areg[j] = v;
    }

    // ---- load SMEM half (g1 rows): As[j*1024 + hh*4+rr] = A[4*row4+rr][j0+j] ----
    for (int rbase = 0; rbase < 4; ++rbase) {
        int ridx = rbase * 256 + tid;            // 0..1023 = hh*4 + rr
        int hh = ridx >> 2, rr = ridx & 3;
        int row4 = (hh >> 5) * 64 + 32 + (hh & 31);
        int grow = 4 * row4 + rr;
        for (int j = 0; j < COLS; ++j)
            As[j * 1024 + ridx] = (j0 + j < Ndim) ? A[grow * Ndim + j0 + j] : 0.0f;
    }

    if (tid < 32) {
        xs[tid] = 0.0f;
        cs[tid] = (tid < myCols) ? c[j0 + tid] : 0.0f;
    }
    const int rb = bid * RPB;
    int nrt = Mdim - rb;
    const int nr = nrt < 0 ? 0 : (nrt < RPB ? nrt : RPB);
    if (tid < nr) {
        float bv = b[rb + tid];
        bloc[tid] = bv; rloc[tid] = bv; uloc[tid] = 0.0f;   // r = s + b - u = b
    }
    __syncthreads();

    const float4* As4 = (const float4*)As;       // index j*256 + h
    float* myPart = g_partial[bid];

    int step = 0;
    for (int it = 0; it < TOTAL_IT; ++it) {
        // ---------------- phase A: partial Ax into g_partial[bid] ----------------
        {
            float xr[COLS];
#pragma unroll
            for (int j = 0; j < COLS; ++j) xr[j] = xs[j];
            float4 a0 = make_float4(0.f, 0.f, 0.f, 0.f);
            float4 a1 = make_float4(0.f, 0.f, 0.f, 0.f);
#pragma unroll
            for (int j = 0; j < COLS; ++j) {
                float xv = xr[j];
                float4 u0 = areg[j];
                float4 u1 = As4[j * 256 + h];
                a0.x = fmaf(u0.x, xv, a0.x);
                a0.y = fmaf(u0.y, xv, a0.y);
                a0.z = fmaf(u0.z, xv, a0.z);
                a0.w = fmaf(u0.w, xv, a0.w);
                a1.x = fmaf(u1.x, xv, a1.x);
                a1.y = fmaf(u1.y, xv, a1.y);
                a1.z = fmaf(u1.z, xv, a1.z);
                a1.w = fmaf(u1.w, xv, a1.w);
            }
            ((float4*)myPart)[g0] = a0;
            ((float4*)myPart)[g1] = a1;
        }
        gbar(g_flags1, base1 + (unsigned)it + 1u);

        // ------------- owner reduce: rows rb..rb+nr-1 across NB partials ---------
        if (tid < NB) {
            const float* p = &g_partial[tid][rb];
#pragma unroll
            for (int ii = 0; ii < RPB; ++ii)
                if (ii < nr) sred[tid * RPB + ii] = __ldcg(p + ii);
        }
        __syncthreads();

        const bool epi = (step == INNER_IT);
#pragma unroll
        for (int pass = 0; pass < 2; ++pass) {
            int ii = w + 8 * pass;
            if (ii < nr) {
                float v = 0.0f;
#pragma unroll
                for (int m = 0; m < 5; ++m) {
                    int k = lane + 32 * m;
                    if (k < NB) v += sred[k * RPB + ii];
                }
                v += __shfl_xor_sync(0xffffffffu, v, 16);
                v += __shfl_xor_sync(0xffffffffu, v, 8);
                v += __shfl_xor_sync(0xffffffffu, v, 4);
                v += __shfl_xor_sync(0xffffffffu, v, 2);
                v += __shfl_xor_sync(0xffffffffu, v, 1);
                if (lane == 0) {
                    int row = rb + ii;
                    if (!epi) {
                        g_e[row] = v - rloc[ii];                  // e = Ax - r
                    } else {
                        float ui = uloc[ii], bv = bloc[ii];
                        float sn = fmaxf(v - bv + ui, 0.0f);      // slack update
                        float un = ui + (v - sn - bv);            // dual update
                        uloc[ii] = un;
                        rloc[ii] = sn + bv - un;                  // r = s + b - u
                        if (it == TOTAL_IT - 1) {
                            out[Ndim + row]            = sn;          // s
                            out[Ndim + Mdim + row]     = un;          // u
                            out[Ndim + 2 * Mdim + row] = -RHO_C * un; // lambda_kkt
                        }
                    }
                }
            }
        }
        gbar(g_flags2, base2 + (unsigned)it + 1u);

        // ---------------- phase B: g = c + rho*A^T e; x = max(x - step*g, 0) -----
        if (!epi) {
            const float4* e4 = (const float4*)g_e;
            float4 e0 = __ldcg(e4 + g0);
            float4 e1 = __ldcg(e4 + g1);
            float acc[COLS];
#pragma unroll
            for (int j = 0; j < COLS; ++j) {
                float4 u0 = areg[j];
                float4 u1 = As4[j * 256 + h];
                float s = u0.x * e0.x;
                s = fmaf(u0.y, e0.y, s);
                s = fmaf(u0.z, e0.z, s);
                s = fmaf(u0.w, e0.w, s);
                s = fmaf(u1.x, e1.x, s);
                s = fmaf(u1.y, e1.y, s);
                s = fmaf(u1.z, e1.z, s);
                s = fmaf(u1.w, e1.w, s);
                acc[j] = s;
            }
#pragma unroll
            for (int j = 0; j < COLS; ++j) {
                float v = acc[j];
                v += __shfl_xor_sync(0xffffffffu, v, 16);
                v += __shfl_xor_sync(0xffffffffu, v, 8);
                v += __shfl_xor_sync(0xffffffffu, v, 4);
                v += __shfl_xor_sync(0xffffffffu, v, 2);
                v += __shfl_xor_sync(0xffffffffu, v, 1);
                if (lane == 0) red[j * NWARP + w] = v;
            }
            __syncthreads();
            if (tid < COLS) {
                float g = 0.0f;
#pragma unroll
                for (int ww = 0; ww < NWARP; ++ww) g += red[tid * NWARP + ww];
                float xn = xs[tid] - STEP_C * (cs[tid] + RHO_C * g);
                xs[tid] = fmaxf(xn, 0.0f);
            }
            __syncthreads();
            ++step;
        } else {
            step = 0;
        }
    }

    // final x (block-local)
    if (tid < myCols) out[j0 + tid] = xs[tid];
}

extern "C" void kernel_launch(void* const* d_in, const int* in_sizes, int n_in,
                              void* d_out, int out_size) {
    const float* A = nullptr;
    const float* b = nullptr;
    const float* c = nullptr;
    for (int k = 0; k < n_in; ++k) {
        if (in_sizes[k] == Mdim * Ndim)      A = (const float*)d_in[k];
        else if (in_sizes[k] == Mdim)        b = (const float*)d_in[k];
        else if (in_sizes[k] == Ndim)        c = (const float*)d_in[k];
    }
    float* out = (float*)d_out;
    size_t shmem = (size_t)(COLS * 1024 + 32 + 32 + COLS * NWARP
                            + NB * RPB + 3 * RPB) * sizeof(float); // 124,240 B
    cudaFuncSetAttribute(admm_persistent,
                         cudaFuncAttributeMaxDynamicSharedMemorySize, (int)shmem);
    admm_persistent<<<NB, NT, shmem>>>(A, b, c, out);
}

// round 3
// speedup vs baseline: 3.0837x; 3.0837x over previous
#include <cuda_runtime.h>
#include <cuda_bf16.h>

#define Mdim 2048
#define Ndim 4096
#define COLS 28          // columns of A owned per block
#define NB   147         // ceil(4096/28)
#define NT   256
#define NWARP 8
#define OUTER_IT 100
#define INNER_IT 20
#define TOTAL_IT (OUTER_IT * (INNER_IT + 1))
#define RHO_C  1.0f
#define STEP_C 5e-5f
#define RPB 14           // rows owned per block (resets/epilogue): 147*14 >= 2048

// Global state (device globals: no allocation allowed)
__device__ __align__(16) float g_ybuf[3][Mdim];   // rotating Ax accumulators
__device__ __align__(16) float g_r[Mdim];         // r = s + b - u
__device__ float g_u[Mdim];
__device__ unsigned g_flags[NB];                  // barrier generation flags

__device__ __forceinline__ unsigned ldflag(const unsigned* p) {
    unsigned v;
    asm volatile("ld.global.cg.u32 %0, [%1];" : "=r"(v) : "l"(p));
    return v;
}

// Flag-array grid barrier: parallel arrival stores, warp-0 sticky polling,
// wrap-safe generation compare.
__device__ __forceinline__ void gbar(unsigned gen) {
    __threadfence();
    __syncthreads();
    if (threadIdx.x == 0)
        asm volatile("st.global.cg.u32 [%0], %1;"
                     :: "l"(&g_flags[blockIdx.x]), "r"(gen) : "memory");
    if (threadIdx.x < 32) {
        unsigned pend = 0;
#pragma unroll
        for (int m = 0; m < 5; ++m)
            if ((int)threadIdx.x + 32 * m < NB) pend |= 1u << m;
        for (;;) {
#pragma unroll
            for (int m = 0; m < 5; ++m)
                if (pend & (1u << m)) {
                    unsigned v = ldflag(&g_flags[threadIdx.x + 32 * m]);
                    if ((int)(v - gen) >= 0) pend &= ~(1u << m);
                }
            if (__all_sync(0xffffffffu, pend == 0)) break;
        }
    }
    __syncthreads();
}

// Vector f32x4 reduction into global (sm_90+)
__device__ __forceinline__ void red4(float* p, float4 v) {
    asm volatile("red.global.add.v4.f32 [%0], {%1, %2, %3, %4};"
                 :: "l"(p), "f"(v.x), "f"(v.y), "f"(v.z), "f"(v.w) : "memory");
}

extern "C" __global__ void __launch_bounds__(NT, 1)
admm_persistent(const float* __restrict__ A,
                const float* __restrict__ b,
                const float* __restrict__ c,
                float* __restrict__ out)
{
    extern __shared__ float sm[];
    float* As  = sm;                      // COLS * Mdim floats, column-major A slice
    float* xs  = sm + COLS * Mdim;        // 32: x chunk
    float* cs  = xs + 32;                 // 32: c chunk
    float* red = cs + 32;                 // COLS * NWARP reduction scratch

    const int tid  = threadIdx.x;
    const int w    = tid >> 5;
    const int lane = tid & 31;
    const int bid  = blockIdx.x;
    const int j0   = bid * COLS;
    const int myCols = (Ndim - j0) < COLS ? (Ndim - j0) : COLS;
    const int g0 = w * 64 + lane;         // float4 row-group index
    const int g1 = g0 + 32;

    // Generation base (monotonic across graph replays; all flags equal at entry)
    const unsigned base = ldflag(&g_flags[bid]);

    // ---- startup: load A column slice into SMEM (zero-padded), init state ----
    for (int idx = tid; idx < COLS * Mdim; idx += NT) {
        int i  = idx / COLS;
        int jj = idx - i * COLS;
        As[jj * Mdim + i] = (jj < myCols) ? A[(size_t)i * Ndim + (j0 + jj)] : 0.0f;
    }
    if (tid < 32) {
        xs[tid] = 0.0f;
        cs[tid] = (tid < myCols) ? c[j0 + tid] : 0.0f;
    }
    const int rb = bid * RPB;
    int nrt = Mdim - rb;
    const int nr = nrt < 0 ? 0 : (nrt < RPB ? nrt : RPB);
    for (int ii = tid; ii < nr; ii += NT) {
        int i = rb + ii;
        float bv = b[i];
        g_u[i] = 0.0f;
        g_r[i] = bv;                     // r = s + b - u = b initially
        __stcg(&g_ybuf[0][i], 0.0f);
        __stcg(&g_ybuf[1][i], 0.0f);
        __stcg(&g_ybuf[2][i], 0.0f);
    }
    gbar(base + 1u);

    const float4* As4 = (const float4*)As;   // index j*512 + g

    int bsel = 0, step = 0;
    for (int it = 0; it < TOTAL_IT; ++it) {
        // ---------------- phase A: partial Ax, RED into g_ybuf[bsel] ------------
        {
            float* yb = g_ybuf[bsel];
            float xr[COLS];
#pragma unroll
            for (int j = 0; j < COLS; ++j) xr[j] = xs[j];
            float4 a0 = make_float4(0.f, 0.f, 0.f, 0.f);
            float4 a1 = make_float4(0.f, 0.f, 0.f, 0.f);
#pragma unroll
            for (int j = 0; j < COLS; ++j) {
                float4 v0 = As4[j * 512 + g0];
                float4 v1 = As4[j * 512 + g1];
                float xv = xr[j];
                a0.x = fmaf(v0.x, xv, a0.x);
                a0.y = fmaf(v0.y, xv, a0.y);
                a0.z = fmaf(v0.z, xv, a0.z);
                a0.w = fmaf(v0.w, xv, a0.w);
                a1.x = fmaf(v1.x, xv, a1.x);
                a1.y = fmaf(v1.y, xv, a1.y);
                a1.z = fmaf(v1.z, xv, a1.z);
                a1.w = fmaf(v1.w, xv, a1.w);
            }
            red4(&yb[4 * g0], a0);
            red4(&yb[4 * g1], a1);
        }
        gbar(base + 2u + (unsigned)it);      // the ONLY grid sync per iteration

        const float* yb = g_ybuf[bsel];
        float* zb = g_ybuf[bsel >= 1 ? bsel - 1 : 2];   // (bsel+2)%3: reset target

        if (step < INNER_IT) {
            // ------------- phase B: g = c + rho*A^T(Ax - r); x = max(x-step*g,0)
            float4 y0 = __ldcg((const float4*)yb + g0);
            float4 r0 = __ldcg((const float4*)g_r + g0);
            float4 y1 = __ldcg((const float4*)yb + g1);
            float4 r1 = __ldcg((const float4*)g_r + g1);
            float4 e0 = make_float4(y0.x - r0.x, y0.y - r0.y, y0.z - r0.z, y0.w - r0.w);
            float4 e1 = make_float4(y1.x - r1.x, y1.y - r1.y, y1.z - r1.z, y1.w - r1.w);
            float acc[COLS];
#pragma unroll
            for (int j = 0; j < COLS; ++j) {
                float4 v0 = As4[j * 512 + g0];
                float4 v1 = As4[j * 512 + g1];
                float s = v0.x * e0.x;
                s = fmaf(v0.y, e0.y, s);
                s = fmaf(v0.z, e0.z, s);
                s = fmaf(v0.w, e0.w, s);
                s = fmaf(v1.x, e1.x, s);
                s = fmaf(v1.y, e1.y, s);
                s = fmaf(v1.z, e1.z, s);
                s = fmaf(v1.w, e1.w, s);
                acc[j] = s;
            }
#pragma unroll
            for (int j = 0; j < COLS; ++j) {
                float v = acc[j];
                v += __shfl_xor_sync(0xffffffffu, v, 16);
                v += __shfl_xor_sync(0xffffffffu, v, 8);
                v += __shfl_xor_sync(0xffffffffu, v, 4);
                v += __shfl_xor_sync(0xffffffffu, v, 2);
                v += __shfl_xor_sync(0xffffffffu, v, 1);
                if (lane == 0) red[j * NWARP + w] = v;
            }
            // reset the buffer accumulated 2 iterations from now (safe: post-barrier)
            for (int ii = tid; ii < nr; ii += NT) __stcg(&zb[rb + ii], 0.0f);
            __syncthreads();
            if (tid < COLS) {
                float g = 0.0f;
#pragma unroll
                for (int ww = 0; ww < NWARP; ++ww) g += red[tid * NWARP + ww];
                float xn = xs[tid] - STEP_C * (cs[tid] + RHO_C * g);
                xs[tid] = fmaxf(xn, 0.0f);
            }
            __syncthreads();
            ++step;
        } else {
            // ------------- epilogue: s, u, r updates (row-owned) ---------------
            for (int ii = tid; ii < nr; ii += NT) {
                int i = rb + ii;
                float Ax = __ldcg(&yb[i]);
                float bi = b[i];
                float ui = g_u[i];
                float sn = fmaxf(Ax - bi + ui, 0.0f);
                float un = ui + (Ax - sn - bi);
                g_u[i] = un;
                g_r[i] = sn + bi - un;           // r = s + b - u
                __stcg(&zb[i], 0.0f);
                if (it == TOTAL_IT - 1) {
                    out[Ndim + i]            = sn;          // s
                    out[Ndim + Mdim + i]     = un;          // u
                    out[Ndim + 2 * Mdim + i] = -RHO_C * un; // lambda_kkt
                }
            }
            step = 0;
        }
        bsel = (bsel + 1 == 3) ? 0 : bsel + 1;
    }

    // final x (block-local)
    if (tid < myCols) out[j0 + tid] = xs[tid];
}

extern "C" void kernel_launch(void* const* d_in, const int* in_sizes, int n_in,
                              void* d_out, int out_size) {
    const float* A = nullptr;
    const float* b = nullptr;
    const float* c = nullptr;
    for (int k = 0; k < n_in; ++k) {
        if (in_sizes[k] == Mdim * Ndim)      A = (const float*)d_in[k];
        else if (in_sizes[k] == Mdim)        b = (const float*)d_in[k];
        else if (in_sizes[k] == Ndim)        c = (const float*)d_in[k];
    }
    float* out = (float*)d_out;
    size_t shmem = (size_t)(COLS * Mdim + 32 + 32 + COLS * NWARP) * sizeof(float);
    cudaFuncSetAttribute(admm_persistent,
                         cudaFuncAttributeMaxDynamicSharedMemorySize, (int)shmem);
    admm_persistent<<<NB, NT, shmem>>>(A, b, c, out);
}